// round 17
// baseline (speedup 1.0000x reference)
#include <cuda_runtime.h>
#include <cuda_fp16.h>
#include <cstdint>

#define N_NODES 100000
#define N_EDGES 1600000
#define FEAT 128
#define NCAT 512
#define M_TILES ((N_NODES + 127) / 128)
#define PAD_K 136   // fp16 elements per SMEM row (272B: 16B-aligned, conflict-free frags)

// ---------------- scratch (static __device__, no allocation) ----------------
__device__ __align__(16) float g_qsk[(size_t)N_NODES * 256];   // [node][q(128)|sk(128)] fp32, streamed
__device__ __align__(16) __half g_kvh[(size_t)N_NODES * 256];  // [node][32 x (k4|v4)] fp16, gather set (51MB)
__device__ __align__(16) float g_h1[N_NODES * FEAT];
__device__ __align__(16) __half g_wbh[2][NCAT * FEAT];  // per-layer B[n][k] = W[k][n], fp16 hi
__device__ __align__(16) __half g_wbl[2][NCAT * FEAT];  // fp16 lo (used by skip block only)
__device__ __align__(16) float g_bias[2][NCAT];
__device__ int g_counts[N_NODES];     // zero-init at load; scan re-zeroes after consuming
__device__ int g_rowoff[N_NODES + 1];
__device__ int g_cursor[N_NODES];
__device__ int g_csrsrc[N_EDGES];

// ---------------- CSR build (edge_index is int32) ----------------
__global__ void count_kernel(const int* __restrict__ ei) {
    int e = blockIdx.x * blockDim.x + threadIdx.x;
    if (e < N_EDGES) atomicAdd(&g_counts[ei[N_EDGES + e]], 1);
}
__global__ void scan_kernel() {
    __shared__ int sums[1024];
    int tid = threadIdx.x;
    const int chunk = (N_NODES + 1023) / 1024;
    int begin = tid * chunk;
    int end = begin + chunk; if (end > N_NODES) end = N_NODES;
    int s = 0;
    int local[98];   // chunk = 98
    for (int i = begin; i < end; i++) {
        int c = g_counts[i];
        g_counts[i] = 0;          // self-clean for next graph replay
        local[i - begin] = c;
        s += c;
    }
    sums[tid] = s;
    __syncthreads();
    for (int off = 1; off < 1024; off <<= 1) {
        int v = (tid >= off) ? sums[tid - off] : 0;
        __syncthreads();
        sums[tid] += v;
        __syncthreads();
    }
    int run = (tid == 0) ? 0 : sums[tid - 1];
    for (int i = begin; i < end; i++) {
        g_rowoff[i] = run;
        g_cursor[i] = run;
        run += local[i - begin];
    }
    if (tid == 1023) g_rowoff[N_NODES] = run;
}
__global__ void scatter_kernel(const int* __restrict__ ei) {
    int e = blockIdx.x * blockDim.x + threadIdx.x;
    if (e < N_EDGES) {
        int pos = atomicAdd(&g_cursor[ei[N_EDGES + e]], 1);
        g_csrsrc[pos] = ei[e];
    }
}

// ---------------- weight prep: both layers in ONE launch ----------------
__global__ void convert_w_all_kernel(
    const float* __restrict__ W10, const float* __restrict__ W11,
    const float* __restrict__ W12, const float* __restrict__ W13,
    const float* __restrict__ b10, const float* __restrict__ b11,
    const float* __restrict__ b12, const float* __restrict__ b13,
    const float* __restrict__ W20, const float* __restrict__ W21,
    const float* __restrict__ W22, const float* __restrict__ W23,
    const float* __restrict__ b20, const float* __restrict__ b21,
    const float* __restrict__ b22, const float* __restrict__ b23) {
    int gi = blockIdx.x * blockDim.x + threadIdx.x;   // over 2*512*128
    if (gi >= 2 * NCAT * FEAT) return;
    int layer = gi >= NCAT * FEAT;
    int i = gi - layer * NCAT * FEAT;
    int n = i >> 7, k = i & 127;
    int widx = n >> 7, ncol = n & 127;
    const float* W = layer == 0
        ? ((widx == 0) ? W10 : (widx == 1) ? W11 : (widx == 2) ? W12 : W13)
        : ((widx == 0) ? W20 : (widx == 1) ? W21 : (widx == 2) ? W22 : W23);
    float w = W[k * 128 + ncol];
    __half h = __float2half_rn(w);
    g_wbh[layer][i] = h;
    g_wbl[layer][i] = __float2half_rn(w - __half2float(h));
    if (i < NCAT) {
        const float* B = layer == 0
            ? ((i < 128) ? b10 : (i < 256) ? b11 : (i < 384) ? b12 : b13)
            : ((i < 128) ? b20 : (i < 256) ? b21 : (i < 384) ? b22 : b23);
        g_bias[layer][i] = B[i & 127];
    }
}

// ---------------- fp16 mma.sync GEMM with A-reuse over 4 output blocks ----------------
// Terms: q/k/v = 1 (Ah*Bh — outputs are fp16-bound anyway), skip = 3 (exact path).
__device__ __forceinline__ void mma16816(float c[4], uint32_t a0, uint32_t a1, uint32_t a2,
                                         uint32_t a3, uint32_t b0, uint32_t b1) {
    asm volatile(
        "mma.sync.aligned.m16n8k16.row.col.f32.f16.f16.f32 "
        "{%0,%1,%2,%3}, {%4,%5,%6,%7}, {%8,%9}, {%0,%1,%2,%3};"
        : "+f"(c[0]), "+f"(c[1]), "+f"(c[2]), "+f"(c[3])
        : "r"(a0), "r"(a1), "r"(a2), "r"(a3), "r"(b0), "r"(b1));
}
__device__ __forceinline__ uint32_t smem_u32(const void* p) {
    uint32_t a;
    asm("{ .reg .u64 t; cvta.to.shared.u64 t, %1; cvt.u32.u64 %0, t; }" : "=r"(a) : "l"(p));
    return a;
}
__device__ __forceinline__ void cp16(uint32_t s, const void* g) {
    asm volatile("cp.async.ca.shared.global [%0], [%1], 16;" :: "r"(s), "l"(g));
}
#define CP_COMMIT() asm volatile("cp.async.commit_group;" ::: "memory")
#define CP_WAIT(n)  asm volatile("cp.async.wait_group %0;" :: "n"(n) : "memory")

#define SM_TILE (128 * PAD_K)   // fp16 elements per tile
#define SMEM_BYTES (6 * SM_TILE * 2)   // [Ah | Al | Bh0 | Bl0 | Bh1 | Bl1]

template <int LAYER>
__device__ __forceinline__ void load_B(int nblk, int buf, uint32_t sb, int tid) {
    uint32_t bh = sb + (2 + 2 * buf) * SM_TILE * 2;
    uint32_t bl = bh + SM_TILE * 2;
    const __half* gh = g_wbh[LAYER] + nblk * 128 * FEAT;
    const __half* gl = g_wbl[LAYER] + nblk * 128 * FEAT;
    bool need_lo = (nblk == 3);
#pragma unroll
    for (int it = 0; it < 8; it++) {
        int p = tid + 256 * it;          // 0..2047
        int row = p >> 4, k8 = p & 15;
        uint32_t so = (uint32_t)(row * PAD_K + k8 * 8) * 2;
        cp16(bh + so, gh + p * 8);
        if (need_lo) cp16(bl + so, gl + p * 8);
    }
}

template <int SRC>
__global__ void __launch_bounds__(256, 1)
gemm_mma_kernel(const float* __restrict__ Xin) {
    extern __shared__ __half sm[];
    __half* sAh = sm;
    __half* sAl = sm + SM_TILE;
    uint32_t sb = smem_u32(sm);

    const float* X = (SRC == 0) ? Xin : (const float*)g_h1;
    int tid = threadIdx.x;
    int wid = tid >> 5, lane = tid & 31;
    int m0 = blockIdx.x * 128;

    load_B<SRC>(0, 0, sb, tid);
    CP_COMMIT();

    // A: load fp32 (streaming), split to fp16 hi/lo in registers, stage to smem
    const float4* X4 = (const float4*)X;
#pragma unroll
    for (int it = 0; it < 16; it++) {
        int q = tid + 256 * it;          // 0..4095
        int row = q >> 5, c4 = q & 31;
        int rg = m0 + row; if (rg > N_NODES - 1) rg = N_NODES - 1;
        float4 f = __ldcs(X4 + (size_t)rg * 32 + c4);
        __half h0 = __float2half_rn(f.x);
        __half h1 = __float2half_rn(f.y);
        __half h2 = __float2half_rn(f.z);
        __half h3 = __float2half_rn(f.w);
        __half l0 = __float2half_rn(f.x - __half2float(h0));
        __half l1 = __float2half_rn(f.y - __half2float(h1));
        __half l2 = __float2half_rn(f.z - __half2float(h2));
        __half l3 = __float2half_rn(f.w - __half2float(h3));
        __half2 hp0(h0, h1), hp1(h2, h3), lp0(l0, l1), lp1(l2, l3);
        uint2 hv, lv;
        hv.x = *(uint32_t*)&hp0; hv.y = *(uint32_t*)&hp1;
        lv.x = *(uint32_t*)&lp0; lv.y = *(uint32_t*)&lp1;
        int eo = row * PAD_K + c4 * 4;
        *(uint2*)&sAh[eo] = hv;
        *(uint2*)&sAl[eo] = lv;
    }

    load_B<SRC>(1, 1, sb, tid);
    CP_COMMIT();
    CP_WAIT(1);
    __syncthreads();

    int wm = wid >> 2, wn = wid & 3;
    int qid = lane >> 2, tq = (lane & 3) * 2;

    for (int nblk = 0; nblk < 4; nblk++) {
        __half* sBh = sm + (2 + 2 * (nblk & 1)) * SM_TILE;
        __half* sBl = sBh + SM_TILE;
        bool full = (nblk == 3);   // skip path: 3-term accuracy

        float c[4][4][4];
#pragma unroll
        for (int i = 0; i < 4; i++)
#pragma unroll
            for (int j = 0; j < 4; j++)
#pragma unroll
                for (int r = 0; r < 4; r++) c[i][j][r] = 0.f;

#pragma unroll
        for (int ks = 0; ks < 8; ks++) {
            int kb = ks * 16;
            uint32_t ah[4][4], al[4][4], bh[4][2], bl[4][2];
#pragma unroll
            for (int i = 0; i < 4; i++) {
                int r0 = (wm * 64 + i * 16 + qid) * PAD_K;
                int r8 = r0 + 8 * PAD_K;
                ah[i][0] = *(const uint32_t*)&sAh[r0 + kb + tq];
                ah[i][1] = *(const uint32_t*)&sAh[r8 + kb + tq];
                ah[i][2] = *(const uint32_t*)&sAh[r0 + kb + 8 + tq];
                ah[i][3] = *(const uint32_t*)&sAh[r8 + kb + 8 + tq];
                if (full) {
                    al[i][0] = *(const uint32_t*)&sAl[r0 + kb + tq];
                    al[i][1] = *(const uint32_t*)&sAl[r8 + kb + tq];
                    al[i][2] = *(const uint32_t*)&sAl[r0 + kb + 8 + tq];
                    al[i][3] = *(const uint32_t*)&sAl[r8 + kb + 8 + tq];
                }
            }
#pragma unroll
            for (int j = 0; j < 4; j++) {
                int n0 = (wn * 32 + j * 8 + qid) * PAD_K;
                bh[j][0] = *(const uint32_t*)&sBh[n0 + kb + tq];
                bh[j][1] = *(const uint32_t*)&sBh[n0 + kb + 8 + tq];
                if (full) {
                    bl[j][0] = *(const uint32_t*)&sBl[n0 + kb + tq];
                    bl[j][1] = *(const uint32_t*)&sBl[n0 + kb + 8 + tq];
                }
            }
#pragma unroll
            for (int i = 0; i < 4; i++)
#pragma unroll
                for (int j = 0; j < 4; j++) {
                    mma16816(c[i][j], ah[i][0], ah[i][1], ah[i][2], ah[i][3], bh[j][0], bh[j][1]);
                    if (full) {
                        mma16816(c[i][j], al[i][0], al[i][1], al[i][2], al[i][3], bh[j][0], bh[j][1]);
                        mma16816(c[i][j], ah[i][0], ah[i][1], ah[i][2], ah[i][3], bl[j][0], bl[j][1]);
                    }
                }
        }

        // epilogue routing:
        //   q (0), sk (3) -> fp32 g_qsk (streaming store) at col offset 0 / 128
        //   k (1), v (2)  -> fp16 g_kvh interleaved (default store: keep L2-resident)
        bool is_qsk = (nblk == 0 || nblk == 3);
        int colofs = (nblk == 3) ? 128 : 0;
        int sel = (nblk == 2) ? 1 : 0;
#pragma unroll
        for (int i = 0; i < 4; i++) {
            int row = m0 + wm * 64 + i * 16 + qid;
#pragma unroll
            for (int j = 0; j < 4; j++) {
                int col = wn * 32 + j * 8 + tq;   // even, pair (col, col+1) in same 4-chunk
                float2 bb = *(const float2*)&g_bias[SRC][nblk * 128 + col];
                float2 o0 = {c[i][j][0] + bb.x, c[i][j][1] + bb.y};
                float2 o1 = {c[i][j][2] + bb.x, c[i][j][3] + bb.y};
                if (is_qsk) {
                    if (row < N_NODES)
                        __stcs((float2*)&g_qsk[(size_t)row * 256 + colofs + col], o0);
                    if (row + 8 < N_NODES)
                        __stcs((float2*)&g_qsk[(size_t)(row + 8) * 256 + colofs + col], o1);
                } else {
                    uint32_t eo = (uint32_t)((col >> 2) * 8 + sel * 4 + (col & 3));
                    if (row < N_NODES) {
                        __half2 p = __floats2half2_rn(o0.x, o0.y);
                        *(__half2*)&g_kvh[(size_t)row * 256 + eo] = p;
                    }
                    if (row + 8 < N_NODES) {
                        __half2 p = __floats2half2_rn(o1.x, o1.y);
                        *(__half2*)&g_kvh[(size_t)(row + 8) * 256 + eo] = p;
                    }
                }
            }
        }

        if (nblk < 3) {
            __syncthreads();
            if (nblk + 2 <= 3) {
                load_B<SRC>(nblk + 2, nblk & 1, sb, tid);
                CP_COMMIT();
                CP_WAIT(1);
            } else {
                CP_WAIT(0);
            }
            __syncthreads();
        }
    }
}

// ---------------- attention core: one LDG.128/edge (fp16 k4|v4), 2-edge pipeline ----------------
__device__ __forceinline__ float4 attn_node(int node, int lane) {
    const float4* qsk = (const float4*)g_qsk;        // 64 float4 per row
    const uint4*  kvh = (const uint4*)g_kvh;         // 32 uint4 per row: [k4(fp16)|v4(fp16)]

    float4 qv = __ldcs(qsk + (size_t)node * 64 + lane);
    qv.x *= 0.125f; qv.y *= 0.125f; qv.z *= 0.125f; qv.w *= 0.125f;  // 1/sqrt(64)

    int e0 = g_rowoff[node];
    int e1 = g_rowoff[node + 1];

    float sA = 0.f, sB = 0.f;
    float4 aA = {0.f, 0.f, 0.f, 0.f}, aB = {0.f, 0.f, 0.f, 0.f};

    int e = e0;
    for (; e + 2 <= e1; e += 2) {
        int s0 = g_csrsrc[e];
        int s1 = g_csrsrc[e + 1];
        uint4 c0 = kvh[(size_t)s0 * 32 + lane];
        uint4 c1 = kvh[(size_t)s1 * 32 + lane];
        float2 k0a = __half22float2(*(__half2*)&c0.x);
        float2 k0b = __half22float2(*(__half2*)&c0.y);
        float2 v0a = __half22float2(*(__half2*)&c0.z);
        float2 v0b = __half22float2(*(__half2*)&c0.w);
        float2 k1a = __half22float2(*(__half2*)&c1.x);
        float2 k1b = __half22float2(*(__half2*)&c1.y);
        float2 v1a = __half22float2(*(__half2*)&c1.z);
        float2 v1b = __half22float2(*(__half2*)&c1.w);
        float d0 = fmaf(qv.x, k0a.x, fmaf(qv.y, k0a.y, fmaf(qv.z, k0b.x, qv.w * k0b.y)));
        float d1 = fmaf(qv.x, k1a.x, fmaf(qv.y, k1a.y, fmaf(qv.z, k1b.x, qv.w * k1b.y)));
        d0 += __shfl_xor_sync(0xffffffffu, d0, 8);
        d1 += __shfl_xor_sync(0xffffffffu, d1, 8);
        d0 += __shfl_xor_sync(0xffffffffu, d0, 4);
        d1 += __shfl_xor_sync(0xffffffffu, d1, 4);
        d0 += __shfl_xor_sync(0xffffffffu, d0, 2);
        d1 += __shfl_xor_sync(0xffffffffu, d1, 2);
        d0 += __shfl_xor_sync(0xffffffffu, d0, 1);
        d1 += __shfl_xor_sync(0xffffffffu, d1, 1);
        float w0 = __expf(d0);
        float w1 = __expf(d1);
        sA += w0; sB += w1;
        aA.x = fmaf(w0, v0a.x, aA.x); aB.x = fmaf(w1, v1a.x, aB.x);
        aA.y = fmaf(w0, v0a.y, aA.y); aB.y = fmaf(w1, v1a.y, aB.y);
        aA.z = fmaf(w0, v0b.x, aA.z); aB.z = fmaf(w1, v1b.x, aB.z);
        aA.w = fmaf(w0, v0b.y, aA.w); aB.w = fmaf(w1, v1b.y, aB.w);
    }
    if (e < e1) {
        int s0 = g_csrsrc[e];
        uint4 c0 = kvh[(size_t)s0 * 32 + lane];
        float2 k0a = __half22float2(*(__half2*)&c0.x);
        float2 k0b = __half22float2(*(__half2*)&c0.y);
        float2 v0a = __half22float2(*(__half2*)&c0.z);
        float2 v0b = __half22float2(*(__half2*)&c0.w);
        float d0 = fmaf(qv.x, k0a.x, fmaf(qv.y, k0a.y, fmaf(qv.z, k0b.x, qv.w * k0b.y)));
        d0 += __shfl_xor_sync(0xffffffffu, d0, 8);
        d0 += __shfl_xor_sync(0xffffffffu, d0, 4);
        d0 += __shfl_xor_sync(0xffffffffu, d0, 2);
        d0 += __shfl_xor_sync(0xffffffffu, d0, 1);
        float w0 = __expf(d0);
        sA += w0;
        aA.x = fmaf(w0, v0a.x, aA.x);
        aA.y = fmaf(w0, v0a.y, aA.y);
        aA.z = fmaf(w0, v0b.x, aA.z);
        aA.w = fmaf(w0, v0b.y, aA.w);
    }

    float s = sA + sB;
    float inv = 1.0f / fmaxf(s, 1e-16f);
    float4 sk = __ldcs(qsk + (size_t)node * 64 + 32 + lane);
    float4 o;
    o.x = fmaf(aA.x + aB.x, inv, sk.x);
    o.y = fmaf(aA.y + aB.y, inv, sk.y);
    o.z = fmaf(aA.z + aB.z, inv, sk.z);
    o.w = fmaf(aA.w + aB.w, inv, sk.w);
    return o;
}

// Layer 1: attn + ELU -> g_h1 (fp32, streaming store; layer-2 GEMM converts inline)
__global__ void attn1_kernel() {
    int node = blockIdx.x * 8 + (threadIdx.x >> 5);   // N_NODES % 8 == 0
    int lane = threadIdx.x & 31;
    float4 o = attn_node(node, lane);
    o.x = (o.x > 0.f) ? o.x : expm1f(o.x);
    o.y = (o.y > 0.f) ? o.y : expm1f(o.y);
    o.z = (o.z > 0.f) ? o.z : expm1f(o.z);
    o.w = (o.w > 0.f) ? o.w : expm1f(o.w);
    __stcs((float4*)g_h1 + (size_t)node * 32 + lane, o);
}

// Layer 2: attn fused with classifier. Wc/bc via __ldg (L1-resident after first block/SM).
// N_NODES % 8 == 0 -> every block has 8 full valid warps (safe __syncthreads).
__global__ void __launch_bounds__(256)
attn2_cls_kernel(const float* __restrict__ Wc, const float* __restrict__ bc,
                 float* __restrict__ out) {
    __shared__ float hs[8][132];   // node stride 132 -> conflict-free column reads

    int tid = threadIdx.x;
    int wib = tid >> 5, lane = tid & 31;
    int node = blockIdx.x * 8 + wib;

    float4 o = attn_node(node, lane);
    hs[wib][lane * 4 + 0] = o.x;
    hs[wib][lane * 4 + 1] = o.y;
    hs[wib][lane * 4 + 2] = o.z;
    hs[wib][lane * 4 + 3] = o.w;
    __syncthreads();

    int base_node = blockIdx.x * 8;
    for (int idx = tid; idx < 320; idx += 256) {
        int n = idx / 40, col = idx - n * 40;
        const float* h = hs[n];
        float a = __ldg(bc + col);
#pragma unroll 8
        for (int k = 0; k < 128; k++) a = fmaf(h[k], __ldg(Wc + k * 40 + col), a);
        out[(size_t)(base_node + n) * 40 + col] = a;
    }
}

// ---------------- launch ----------------
extern "C" void kernel_launch(void* const* d_in, const int* in_sizes, int n_in,
                              void* d_out, int out_size) {
    const float* x   = (const float*)d_in[0];
    const int*   ei  = (const int*)d_in[1];   // int32 (JAX x64-disabled)
    const float* Wq1 = (const float*)d_in[2];  const float* bq1 = (const float*)d_in[3];
    const float* Wk1 = (const float*)d_in[4];  const float* bk1 = (const float*)d_in[5];
    const float* Wv1 = (const float*)d_in[6];  const float* bv1 = (const float*)d_in[7];
    const float* Ws1 = (const float*)d_in[8];  const float* bs1 = (const float*)d_in[9];
    const float* Wq2 = (const float*)d_in[10]; const float* bq2 = (const float*)d_in[11];
    const float* Wk2 = (const float*)d_in[12]; const float* bk2 = (const float*)d_in[13];
    const float* Wv2 = (const float*)d_in[14]; const float* bv2 = (const float*)d_in[15];
    const float* Ws2 = (const float*)d_in[16]; const float* bs2 = (const float*)d_in[17];
    const float* Wc  = (const float*)d_in[18]; const float* bc  = (const float*)d_in[19];
    float* out = (float*)d_out;

    static int configured = 0;
    static cudaStream_t s2;
    static cudaEvent_t evFork, evJoin;
    if (!configured) {
        cudaFuncSetAttribute(gemm_mma_kernel<0>, cudaFuncAttributeMaxDynamicSharedMemorySize,
                             SMEM_BYTES);
        cudaFuncSetAttribute(gemm_mma_kernel<1>, cudaFuncAttributeMaxDynamicSharedMemorySize,
                             SMEM_BYTES);
        cudaStreamCreateWithFlags(&s2, cudaStreamNonBlocking);
        cudaEventCreateWithFlags(&evFork, cudaEventDisableTiming);
        cudaEventCreateWithFlags(&evJoin, cudaEventDisableTiming);
        configured = 1;
    }

    int nattn = N_NODES / 8;   // 12500 full blocks

    // ---- main #1: both layers' weight conversion (one launch) ----
    convert_w_all_kernel<<<(2 * NCAT * FEAT + 255) / 256, 256>>>(
        Wq1, Wk1, Wv1, Ws1, bq1, bk1, bv1, bs1,
        Wq2, Wk2, Wv2, Ws2, bq2, bk2, bv2, bs2);

    // ---- fork: CSR build on side stream (hidden under gemm1) ----
    cudaEventRecord(evFork, 0);
    cudaStreamWaitEvent(s2, evFork, 0);
    count_kernel<<<(N_EDGES + 255) / 256, 256, 0, s2>>>(ei);
    scan_kernel<<<1, 1024, 0, s2>>>();
    scatter_kernel<<<(N_EDGES + 255) / 256, 256, 0, s2>>>(ei);
    cudaEventRecord(evJoin, s2);

    // ---- main: gemm1 ----
    gemm_mma_kernel<0><<<M_TILES, 256, SMEM_BYTES>>>(x);

    // ---- join: attn1 needs CSR + gemm1 ----
    cudaStreamWaitEvent(0, evJoin, 0);
    attn1_kernel<<<nattn, 256>>>();

    // Layer 2 + fused classifier
    gemm_mma_kernel<1><<<M_TILES, 256, SMEM_BYTES>>>(nullptr);
    attn2_cls_kernel<<<nattn, 256>>>(Wc, bc, out);
}